// round 13
// baseline (speedup 1.0000x reference)
#include <cuda_runtime.h>
#include <cuda_bf16.h>

// GivensRotationPerHead: H=64 heads, DIM=128, R=8128 rotations (triu i-major order).
// Round 13:
//   - givens j-sweep: 2-wide j (R9's proven-correct interleave) COMBINED WITH
//     R6's cross-iteration prefetch pipeline (load next vj+coeffs BEFORE the
//     stores -- ptxas cannot hoist smem loads over may-alias smem stores).
//     Breaks the 16-FMA serial chain: ~36cy/j vs ~90cy/j.
//   - combine: R8/R11 K-split 512-thread structural GEMM, UNCHANGED (17.6us).
//     (R12's "diagonal" claim was WRONG -- H0[40:,40:] is lower-triangular.)

#define NHEADS 64
#define DIMN   128
#define NROT   8128
#define TPB    128

#define SPLIT_I   40
#define SPLIT_B   5
#define NB        16
#define R_SPLIT   4300
#define RANGE0    4300
#define RANGE1    3828
#define MAXRANGE  4300
#define MDIM      88        // DIMN - SPLIT_I

__device__ __forceinline__ int rbase(int i) { return i * 127 - (i * (i - 1)) / 2; }
__device__ __forceinline__ int blockbase8(int b) { return 988 * b - 32 * b * (b - 1); }

__device__ __forceinline__ void frot(float& vi, float& vj, float a, float b) {
    float ni = fmaf(a, vj, vi);
    vj = fmaf(b, vi, vj);
    vi = ni;
}

// 8 MB global scratch: halfQ[task][128][128], task = head*2 + half
__device__ float g_halfQ[2 * NHEADS * DIMN * DIMN];

#define OFF_T   MAXRANGE
#define OFF_FI  (2 * MAXRANGE)
#define OFF_FJ  (3 * MAXRANGE)
#define OFF_AB  (4 * MAXRANGE)
#define OFF_RS  (4 * MAXRANGE + 2 * MAXRANGE)
#define SM_FLOATS (OFF_RS + DIMN)     // 25928 floats = 103712 B

__global__ __launch_bounds__(TPB)
void givens_half_kernel(const float* __restrict__ thetas,
                        const int*   __restrict__ rot_i,
                        const int*   __restrict__ rot_j)
{
    extern __shared__ float sm[];
    float*  C  = sm;
    float*  T  = sm + OFF_T;
    float*  Fi = sm + OFF_FI;
    float*  Fj = sm + OFF_FJ;
    float*  Qs = sm;                         // aliases C/T/Fi after pass 3
    float2* AB = (float2*)(sm + OFF_AB);
    float*  rs = sm + OFF_RS;

    const int tid  = threadIdx.x;
    const int task = blockIdx.x;
    const int head = task >> 1;
    const int half = task & 1;

    const int r0    = half ? R_SPLIT : 0;
    const int range = half ? RANGE1 : RANGE0;
    const int b_lo  = half ? SPLIT_B : 0;
    const int b_hi  = half ? NB : SPLIT_B;
    const int ilo   = half ? SPLIT_I : 0;
    const int ihi   = half ? DIMN : SPLIT_I;

    const float* th = thetas + (size_t)head * NROT + r0;

    // ---- pass 1: cos / tan ----
    for (int rl = tid; rl < range; rl += TPB) {
        float s, c;
        __sincosf(th[rl], &s, &c);
        C[rl] = c;
        T[rl] = __fdividef(s, c);
    }
    __syncthreads();

    // ---- pass 2: per-row prefix products (row = tid) ----
    {
        const int m = tid;
        float f = 1.0f;
        int kend = m < ihi ? m : ihi;
        for (int k = ilo; k < kend; ++k) {
            int rl = rbase(k) + (m - k - 1) - r0;
            Fj[rl] = f;
            f *= C[rl];
        }
        if (m >= ilo && m < ihi) {
            int base = rbase(m) - r0;
            for (int j = m + 1; j < DIMN; ++j) {
                int rl = base + (j - m - 1);
                Fi[rl] = f;
                f *= C[rl];
            }
        }
        rs[m] = f;
    }
    __syncthreads();

    // ---- pass 3: alpha/beta into blocked AB table ([j][a], 8 float2 per j) ----
    for (int rl = tid; rl < range; rl += TPB) {
        int r = r0 + rl;
        int i = rot_i[r];
        int j = rot_j[r];
        float t  = T[rl];
        float fi = Fi[rl];
        float fj = Fj[rl];
        float al =  t * __fdividef(fj, fi);
        float be = -t * __fdividef(fi, fj);
        int b  = i >> 3;
        int a  = i & 7;
        int i0 = b << 3;
        int bb = blockbase8(b) - r0;
        int pos;
        if (j < i0 + 8) {
            int jj = j - i0;
            pos = bb + a * 7 - (a * (a - 1)) / 2 + (jj - a - 1);
        } else {
            pos = bb + 28 + ((j - i0 - 8) << 3) + a;
        }
        AB[pos] = make_float2(al, be);
    }
    __syncthreads();

    // ---- init Q~ = I ----
    for (int idx = tid; idx < DIMN * DIMN; idx += TPB)
        Qs[idx] = ((idx >> 7) == (idx & 127)) ? 1.0f : 0.0f;
    __syncthreads();

    // ---- main loop: 8-row register blocks, 2-wide pipelined j-sweep ----
    // Cross-iteration prefetch (loads BEFORE stores in source order) is
    // load-bearing. 2-wide interleave order proven correct in R9/R10.
    // half1 columns < 40 are exact identity; warp 0 (cols 0-31) skips entirely.
    if (!(half && tid < 32)) {
        const int t = tid;
        for (int b = b_lo; b < b_hi; ++b) {
            const int i0 = b << 3;
            const int bb = blockbase8(b) - r0;

            float v[8];
            #pragma unroll
            for (int a = 0; a < 8; ++a) v[a] = Qs[(i0 + a) * DIMN + t];

            // intra-block triangle (28 rotations, original order)
            {
                const float2* abt = AB + bb;
                int p = 0;
                #pragma unroll
                for (int a = 0; a < 7; ++a)
                    #pragma unroll
                    for (int jj = a + 1; jj < 8; ++jj) {
                        float2 ab = abt[p++];
                        frot(v[a], v[jj], ab.x, ab.y);
                    }
            }

            // 2-wide pipelined j-sweep (sweep length divisible by 8 -> by 2)
            if (i0 + 8 < DIMN) {
                int j = i0 + 8;
                float vj0 = Qs[(j + 0) * DIMN + t];
                float vj1 = Qs[(j + 1) * DIMN + t];
                const float4* ap = (const float4*)(AB + bb + 28);
                float4 c0 = ap[0], c1 = ap[1], c2 = ap[2], c3 = ap[3];
                float4 c4 = ap[4], c5 = ap[5], c6 = ap[6], c7 = ap[7];

                for (; j < DIMN; j += 2) {
                    int jn = (j + 2 < DIMN) ? j + 2 : j;   // clamped prefetch
                    const float4* np =
                        (const float4*)(AB + bb + 28 + ((jn - i0 - 8) << 3));
                    float4 n0 = np[0], n1 = np[1], n2 = np[2], n3 = np[3];
                    float4 n4 = np[4], n5 = np[5], n6 = np[6], n7 = np[7];
                    float  w0 = Qs[(jn + 0) * DIMN + t];
                    float  w1 = Qs[(jn + 1) * DIMN + t];

                    // c0..c3 = rows 0..7 @ j ; c4..c7 = rows 0..7 @ j+1
                    frot(v[0], vj0, c0.x, c0.y);
                    frot(v[1], vj0, c0.z, c0.w);
                    frot(v[0], vj1, c4.x, c4.y);
                    frot(v[1], vj1, c4.z, c4.w);

                    frot(v[2], vj0, c1.x, c1.y);
                    frot(v[3], vj0, c1.z, c1.w);
                    frot(v[2], vj1, c5.x, c5.y);
                    frot(v[3], vj1, c5.z, c5.w);

                    frot(v[4], vj0, c2.x, c2.y);
                    frot(v[5], vj0, c2.z, c2.w);
                    frot(v[4], vj1, c6.x, c6.y);
                    frot(v[5], vj1, c6.z, c6.w);

                    frot(v[6], vj0, c3.x, c3.y);
                    frot(v[7], vj0, c3.z, c3.w);
                    frot(v[6], vj1, c7.x, c7.y);
                    frot(v[7], vj1, c7.z, c7.w);

                    Qs[(j + 0) * DIMN + t] = vj0;
                    Qs[(j + 1) * DIMN + t] = vj1;
                    vj0 = w0;  vj1 = w1;
                    c0 = n0; c1 = n1; c2 = n2; c3 = n3;
                    c4 = n4; c5 = n5; c6 = n6; c7 = n7;
                }
            }

            #pragma unroll
            for (int a = 0; a < 8; ++a) Qs[(i0 + a) * DIMN + t] = v[a];
        }
    }
    __syncthreads();

    // ---- write scaled half to global scratch ----
    float* o = g_halfQ + (size_t)task * DIMN * DIMN;
    for (int idx = tid; idx < DIMN * DIMN; idx += TPB)
        o[idx] = rs[idx >> 7] * Qs[idx];
}

// ============================================================================
// Structural combine (R8/R11, measured 17.6us, proven correct):
//   out[0:40, :] = H0[0:40, :]                        (copy, rh=0 CTA)
//   out[40+mb : 40+mb+44, :] = M[mb:mb+44, :] @ H0[40:, :]   (mb = rh*44)
// 512 threads: two 256-thread groups each do half of K (44), partials reduced
// through smem. Per-thread tile 3x8 over 44 GEMM rows (sM padded to 48).
// ============================================================================
#define GTPB 512
#define GSM_B  0
#define GSM_M  (MDIM * DIMN)
#define GSM_P  (MDIM * DIMN + 48 * MDIM)
#define GSM_FLOATS (MDIM * DIMN + 48 * MDIM + 44 * DIMN)   // 21120 fl = 84480 B

__global__ __launch_bounds__(GTPB)
void combine_kernel(float* __restrict__ out)
{
    extern __shared__ float gs[];
    float* sB = gs + GSM_B;      // H0 rows 40..127: [kb][c]
    float* sM = gs + GSM_M;      // M slice: [m][k], rows 44..47 zero
    float* sP = gs + GSM_P;      // partials from K-group 1

    const int tid  = threadIdx.x;
    const int head = blockIdx.x >> 1;
    const int rh   = blockIdx.x & 1;
    const int mb   = rh * 44;

    const float* A = g_halfQ + (size_t)(head * 2 + 0) * DIMN * DIMN;  // H0
    const float* B = g_halfQ + (size_t)(head * 2 + 1) * DIMN * DIMN;  // H1
    float*       O = out + (size_t)head * DIMN * DIMN;

    {
        const float4* src = (const float4*)(A + 40 * DIMN);
        for (int i = tid; i < MDIM * DIMN / 4; i += GTPB)
            ((float4*)sB)[i] = src[i];
    }
    for (int i = tid; i < 4 * MDIM; i += GTPB)
        sM[44 * MDIM + i] = 0.0f;
    for (int i = tid; i < 44 * 22; i += GTPB) {
        int m = i / 22, k4 = i % 22;
        ((float4*)(sM + m * MDIM))[k4] =
            *(const float4*)(B + (size_t)(40 + mb + m) * DIMN + 40 + k4 * 4);
    }
    if (rh == 0) {
        const float4* src = (const float4*)A;
        float4* dst = (float4*)O;
        for (int i = tid; i < 40 * DIMN / 4; i += GTPB)
            dst[i] = src[i];
    }
    __syncthreads();

    const int g    = tid >> 8;          // K-group 0/1
    const int tid2 = tid & 255;
    const int tx   = tid2 & 15;
    const int ty   = tid2 >> 4;
    const int c0   = tx << 3;
    const int m0   = ty * 3;
    const int kb   = g * 44;

    float acc[3][8];
    #pragma unroll
    for (int i = 0; i < 3; ++i)
        #pragma unroll
        for (int j = 0; j < 8; ++j) acc[i][j] = 0.0f;

    float a0 = sM[(m0 + 0) * MDIM + kb];
    float a1 = sM[(m0 + 1) * MDIM + kb];
    float a2 = sM[(m0 + 2) * MDIM + kb];
    float4 b0 = *(const float4*)&sB[kb * DIMN + c0];
    float4 b1 = *(const float4*)&sB[kb * DIMN + c0 + 4];

    #pragma unroll 2
    for (int kk = 0; kk < 44; ++kk) {
        int k  = kb + kk;
        int kn = (kk + 1 < 44) ? k + 1 : k;
        float na0 = sM[(m0 + 0) * MDIM + kn];
        float na1 = sM[(m0 + 1) * MDIM + kn];
        float na2 = sM[(m0 + 2) * MDIM + kn];
        float4 nb0 = *(const float4*)&sB[kn * DIMN + c0];
        float4 nb1 = *(const float4*)&sB[kn * DIMN + c0 + 4];

        acc[0][0] = fmaf(a0, b0.x, acc[0][0]);
        acc[0][1] = fmaf(a0, b0.y, acc[0][1]);
        acc[0][2] = fmaf(a0, b0.z, acc[0][2]);
        acc[0][3] = fmaf(a0, b0.w, acc[0][3]);
        acc[0][4] = fmaf(a0, b1.x, acc[0][4]);
        acc[0][5] = fmaf(a0, b1.y, acc[0][5]);
        acc[0][6] = fmaf(a0, b1.z, acc[0][6]);
        acc[0][7] = fmaf(a0, b1.w, acc[0][7]);

        acc[1][0] = fmaf(a1, b0.x, acc[1][0]);
        acc[1][1] = fmaf(a1, b0.y, acc[1][1]);
        acc[1][2] = fmaf(a1, b0.z, acc[1][2]);
        acc[1][3] = fmaf(a1, b0.w, acc[1][3]);
        acc[1][4] = fmaf(a1, b1.x, acc[1][4]);
        acc[1][5] = fmaf(a1, b1.y, acc[1][5]);
        acc[1][6] = fmaf(a1, b1.z, acc[1][6]);
        acc[1][7] = fmaf(a1, b1.w, acc[1][7]);

        acc[2][0] = fmaf(a2, b0.x, acc[2][0]);
        acc[2][1] = fmaf(a2, b0.y, acc[2][1]);
        acc[2][2] = fmaf(a2, b0.z, acc[2][2]);
        acc[2][3] = fmaf(a2, b0.w, acc[2][3]);
        acc[2][4] = fmaf(a2, b1.x, acc[2][4]);
        acc[2][5] = fmaf(a2, b1.y, acc[2][5]);
        acc[2][6] = fmaf(a2, b1.z, acc[2][6]);
        acc[2][7] = fmaf(a2, b1.w, acc[2][7]);

        a0 = na0; a1 = na1; a2 = na2;
        b0 = nb0; b1 = nb1;
    }

    if (g == 1) {
        #pragma unroll
        for (int i = 0; i < 3; ++i) {
            int m = m0 + i;
            if (m < 44) {
                float* p = sP + m * DIMN + c0;
                *(float4*)p       = make_float4(acc[i][0], acc[i][1], acc[i][2], acc[i][3]);
                *(float4*)(p + 4) = make_float4(acc[i][4], acc[i][5], acc[i][6], acc[i][7]);
            }
        }
    }
    __syncthreads();
    if (g == 0) {
        const int rowbase = 40 + mb;
        #pragma unroll
        for (int i = 0; i < 3; ++i) {
            int m = m0 + i;
            if (m < 44) {
                const float* p = sP + m * DIMN + c0;
                float4 p0 = *(const float4*)p;
                float4 p1 = *(const float4*)(p + 4);
                float* o = O + (size_t)(rowbase + m) * DIMN + c0;
                *(float4*)o = make_float4(acc[i][0] + p0.x, acc[i][1] + p0.y,
                                          acc[i][2] + p0.z, acc[i][3] + p0.w);
                *(float4*)(o + 4) = make_float4(acc[i][4] + p1.x, acc[i][5] + p1.y,
                                                acc[i][6] + p1.z, acc[i][7] + p1.w);
            }
        }
    }
}

extern "C" void kernel_launch(void* const* d_in, const int* in_sizes, int n_in,
                              void* d_out, int out_size)
{
    const float* thetas = (const float*)d_in[0];
    const int*   ri     = (const int*)d_in[1];
    const int*   rj     = (const int*)d_in[2];
    float*       out    = (float*)d_out;

    const size_t smem1 = SM_FLOATS * sizeof(float);    // 103712 B
    const size_t smem2 = GSM_FLOATS * sizeof(float);   //  84480 B
    cudaFuncSetAttribute(givens_half_kernel,
                         cudaFuncAttributeMaxDynamicSharedMemorySize, (int)smem1);
    cudaFuncSetAttribute(combine_kernel,
                         cudaFuncAttributeMaxDynamicSharedMemorySize, (int)smem2);

    givens_half_kernel<<<2 * NHEADS, TPB, smem1>>>(thetas, ri, rj);
    combine_kernel<<<2 * NHEADS, GTPB, smem2>>>(out);
}

// round 14
// speedup vs baseline: 1.0447x; 1.0447x over previous
#include <cuda_runtime.h>
#include <cuda_bf16.h>

// GivensRotationPerHead: H=64 heads, DIM=128, R=8128 rotations (triu i-major order).
// Round 14:
//   - givens: R11's 1-wide pipelined j-sweep, byte-identical (measured ~26us;
//     chain-width experiments R8/R13 proved it is issue-floor-bound, not
//     chain-bound, at 1 warp/SMSP).
//   - combine: exploits exact lower-triangularity of H0[40:, :] (rows >=40 of
//     H0 are j-role-only => row r support {0..r}): k-loop starts at
//     klo = max(0, c0-40). Column-major warp remap + transposed sM for
//     warp-uniform bounds and conflict-free loads. ~31% fewer GEMM iters.

#define NHEADS 64
#define DIMN   128
#define NROT   8128
#define TPB    128

#define SPLIT_I   40
#define SPLIT_B   5
#define NB        16
#define R_SPLIT   4300
#define RANGE0    4300
#define RANGE1    3828
#define MAXRANGE  4300
#define MDIM      88        // DIMN - SPLIT_I

__device__ __forceinline__ int rbase(int i) { return i * 127 - (i * (i - 1)) / 2; }
__device__ __forceinline__ int blockbase8(int b) { return 988 * b - 32 * b * (b - 1); }

__device__ __forceinline__ void frot(float& vi, float& vj, float a, float b) {
    float ni = fmaf(a, vj, vi);
    vj = fmaf(b, vi, vj);
    vi = ni;
}

// 8 MB global scratch: halfQ[task][128][128], task = head*2 + half
__device__ float g_halfQ[2 * NHEADS * DIMN * DIMN];

#define OFF_T   MAXRANGE
#define OFF_FI  (2 * MAXRANGE)
#define OFF_FJ  (3 * MAXRANGE)
#define OFF_AB  (4 * MAXRANGE)
#define OFF_RS  (4 * MAXRANGE + 2 * MAXRANGE)
#define SM_FLOATS (OFF_RS + DIMN)     // 25928 floats = 103712 B

__global__ __launch_bounds__(TPB)
void givens_half_kernel(const float* __restrict__ thetas,
                        const int*   __restrict__ rot_i,
                        const int*   __restrict__ rot_j)
{
    extern __shared__ float sm[];
    float*  C  = sm;
    float*  T  = sm + OFF_T;
    float*  Fi = sm + OFF_FI;
    float*  Fj = sm + OFF_FJ;
    float*  Qs = sm;                         // aliases C/T/Fi after pass 3
    float2* AB = (float2*)(sm + OFF_AB);
    float*  rs = sm + OFF_RS;

    const int tid  = threadIdx.x;
    const int task = blockIdx.x;
    const int head = task >> 1;
    const int half = task & 1;

    const int r0    = half ? R_SPLIT : 0;
    const int range = half ? RANGE1 : RANGE0;
    const int b_lo  = half ? SPLIT_B : 0;
    const int b_hi  = half ? NB : SPLIT_B;
    const int ilo   = half ? SPLIT_I : 0;
    const int ihi   = half ? DIMN : SPLIT_I;

    const float* th = thetas + (size_t)head * NROT + r0;

    // ---- pass 1: cos / tan ----
    for (int rl = tid; rl < range; rl += TPB) {
        float s, c;
        __sincosf(th[rl], &s, &c);
        C[rl] = c;
        T[rl] = __fdividef(s, c);
    }
    __syncthreads();

    // ---- pass 2: per-row prefix products (row = tid) ----
    {
        const int m = tid;
        float f = 1.0f;
        int kend = m < ihi ? m : ihi;
        for (int k = ilo; k < kend; ++k) {
            int rl = rbase(k) + (m - k - 1) - r0;
            Fj[rl] = f;
            f *= C[rl];
        }
        if (m >= ilo && m < ihi) {
            int base = rbase(m) - r0;
            for (int j = m + 1; j < DIMN; ++j) {
                int rl = base + (j - m - 1);
                Fi[rl] = f;
                f *= C[rl];
            }
        }
        rs[m] = f;
    }
    __syncthreads();

    // ---- pass 3: alpha/beta into blocked AB table ([j][a], 8 float2 per j) ----
    for (int rl = tid; rl < range; rl += TPB) {
        int r = r0 + rl;
        int i = rot_i[r];
        int j = rot_j[r];
        float t  = T[rl];
        float fi = Fi[rl];
        float fj = Fj[rl];
        float al =  t * __fdividef(fj, fi);
        float be = -t * __fdividef(fi, fj);
        int b  = i >> 3;
        int a  = i & 7;
        int i0 = b << 3;
        int bb = blockbase8(b) - r0;
        int pos;
        if (j < i0 + 8) {
            int jj = j - i0;
            pos = bb + a * 7 - (a * (a - 1)) / 2 + (jj - a - 1);
        } else {
            pos = bb + 28 + ((j - i0 - 8) << 3) + a;
        }
        AB[pos] = make_float2(al, be);
    }
    __syncthreads();

    // ---- init Q~ = I ----
    for (int idx = tid; idx < DIMN * DIMN; idx += TPB)
        Qs[idx] = ((idx >> 7) == (idx & 127)) ? 1.0f : 0.0f;
    __syncthreads();

    // ---- main loop: 8-row register blocks, 1-wide j with software pipeline ----
    // Prefetch-next-before-store is load-bearing (smem alias ordering).
    // half1 columns < 40 are exact identity; warp 0 (cols 0-31) skips entirely.
    if (!(half && tid < 32)) {
        const int t = tid;
        for (int b = b_lo; b < b_hi; ++b) {
            const int i0 = b << 3;
            const int bb = blockbase8(b) - r0;

            float v[8];
            #pragma unroll
            for (int a = 0; a < 8; ++a) v[a] = Qs[(i0 + a) * DIMN + t];

            // intra-block triangle (28 rotations, original order)
            {
                const float2* abt = AB + bb;
                int p = 0;
                #pragma unroll
                for (int a = 0; a < 7; ++a)
                    #pragma unroll
                    for (int jj = a + 1; jj < 8; ++jj) {
                        float2 ab = abt[p++];
                        frot(v[a], v[jj], ab.x, ab.y);
                    }
            }

            // j-sweep with software pipeline (prefetch next vj + AB before store)
            if (i0 + 8 < DIMN) {
                int j = i0 + 8;
                float vj = Qs[j * DIMN + t];
                const float4* ap = (const float4*)(AB + bb + 28);
                float4 a0 = ap[0], a1 = ap[1], a2 = ap[2], a3 = ap[3];

                #pragma unroll 2
                for (; j < DIMN; ++j) {
                    int jn = (j + 1 < DIMN) ? j + 1 : j;            // clamped prefetch
                    const float4* np =
                        (const float4*)(AB + bb + 28 + ((jn - i0 - 8) << 3));
                    float4 n0 = np[0], n1 = np[1], n2 = np[2], n3 = np[3];
                    float  vn = Qs[jn * DIMN + t];

                    frot(v[0], vj, a0.x, a0.y);
                    frot(v[1], vj, a0.z, a0.w);
                    frot(v[2], vj, a1.x, a1.y);
                    frot(v[3], vj, a1.z, a1.w);
                    frot(v[4], vj, a2.x, a2.y);
                    frot(v[5], vj, a2.z, a2.w);
                    frot(v[6], vj, a3.x, a3.y);
                    frot(v[7], vj, a3.z, a3.w);

                    Qs[j * DIMN + t] = vj;
                    vj = vn;
                    a0 = n0; a1 = n1; a2 = n2; a3 = n3;
                }
            }

            #pragma unroll
            for (int a = 0; a < 8; ++a) Qs[(i0 + a) * DIMN + t] = v[a];
        }
    }
    __syncthreads();

    // ---- write scaled half to global scratch ----
    float* o = g_halfQ + (size_t)task * DIMN * DIMN;
    for (int idx = tid; idx < DIMN * DIMN; idx += TPB)
        o[idx] = rs[idx >> 7] * Qs[idx];
}

// ============================================================================
// Structural combine v3 (triangular H0 lower block):
//   out[0:40, :] = H0[0:40, :]                        (copy, rh=0 CTA)
//   out[40+mb+m][c] = sum_{k>=klo(c)} M[mb+m][k] * H0[40+k][c],
//     klo(c-group) = max(0, c0-40)  (H0[40+k][c]=0 for c>40+k, exact zeros)
// 512 threads, K-group split over [klo, 88). Column-major warp remap:
//   txg = (tid2>>4) col-group, ty = (tid2&15) row-group -> warp-uniform klo.
// sMT stores M transposed [k][m] (stride 48) for conflict-free scalar loads.
// ============================================================================
#define GTPB 512
#define MTS    48                                  // sMT row stride
#define GSM_B  0                                   // sB  [88][128]
#define GSM_MT (MDIM * DIMN)                       // sMT [88][48]
#define GSM_P  (MDIM * DIMN + MDIM * MTS)          // sP  [44][128]
#define GSM_FLOATS (MDIM * DIMN + MDIM * MTS + 44 * DIMN)  // 21120 fl = 84480 B

__global__ __launch_bounds__(GTPB)
void combine_kernel(float* __restrict__ out)
{
    extern __shared__ float gs[];
    float* sB  = gs + GSM_B;     // H0 rows 40..127: [k][c]
    float* sMT = gs + GSM_MT;    // M slice transposed: [k][m], m 44..47 zero
    float* sP  = gs + GSM_P;     // partials from K-group 1

    const int tid  = threadIdx.x;
    const int head = blockIdx.x >> 1;
    const int rh   = blockIdx.x & 1;
    const int mb   = rh * 44;

    const float* A = g_halfQ + (size_t)(head * 2 + 0) * DIMN * DIMN;  // H0
    const float* B = g_halfQ + (size_t)(head * 2 + 1) * DIMN * DIMN;  // H1
    float*       O = out + (size_t)head * DIMN * DIMN;

    // sB: H0[40:128][:] = 2816 float4
    {
        const float4* src = (const float4*)(A + 40 * DIMN);
        for (int i = tid; i < MDIM * DIMN / 4; i += GTPB)
            ((float4*)sB)[i] = src[i];
    }
    // sMT[k][m] = M[mb+m][k] = H1[40+mb+m][40+k]; k fastest -> coalesced reads
    for (int i = tid; i < MDIM * 44; i += GTPB) {
        int k = i % MDIM, m = i / MDIM;
        sMT[k * MTS + m] = B[(size_t)(40 + mb + m) * DIMN + 40 + k];
    }
    // zero pad m = 44..47
    for (int i = tid; i < MDIM * 4; i += GTPB)
        sMT[(i % MDIM) * MTS + 44 + i / MDIM] = 0.0f;
    // rh=0 CTA copies out rows 0..39 (exact)
    if (rh == 0) {
        const float4* src = (const float4*)A;
        float4* dst = (float4*)O;
        for (int i = tid; i < 40 * DIMN / 4; i += GTPB)
            dst[i] = src[i];
    }
    __syncthreads();

    // GEMM: 44 rows x 128 cols, triangular K range split across 2 groups.
    const int g    = tid >> 8;          // K-group 0/1
    const int tid2 = tid & 255;
    const int txg  = tid2 >> 4;         // col group 0..15 (column-major warps)
    const int ty   = tid2 & 15;         // row group 0..15
    const int c0   = txg << 3;
    const int m0   = ty * 3;

    const int klo  = (c0 > 40) ? (c0 - 40) : 0;   // exact-zero skip
    const int half = (MDIM - klo) >> 1;           // span is even
    const int kbeg = klo + g * half;
    const int kend = g ? MDIM : (klo + half);

    float acc[3][8];
    #pragma unroll
    for (int i = 0; i < 3; ++i)
        #pragma unroll
        for (int j = 0; j < 8; ++j) acc[i][j] = 0.0f;

    {
        const float* mt = sMT + m0;
        float a0 = mt[kbeg * MTS + 0];
        float a1 = mt[kbeg * MTS + 1];
        float a2 = mt[kbeg * MTS + 2];
        float4 b0 = *(const float4*)&sB[kbeg * DIMN + c0];
        float4 b1 = *(const float4*)&sB[kbeg * DIMN + c0 + 4];

        #pragma unroll 2
        for (int k = kbeg; k < kend; ++k) {
            int kn = (k + 1 < kend) ? k + 1 : k;
            float na0 = mt[kn * MTS + 0];
            float na1 = mt[kn * MTS + 1];
            float na2 = mt[kn * MTS + 2];
            float4 nb0 = *(const float4*)&sB[kn * DIMN + c0];
            float4 nb1 = *(const float4*)&sB[kn * DIMN + c0 + 4];

            acc[0][0] = fmaf(a0, b0.x, acc[0][0]);
            acc[0][1] = fmaf(a0, b0.y, acc[0][1]);
            acc[0][2] = fmaf(a0, b0.z, acc[0][2]);
            acc[0][3] = fmaf(a0, b0.w, acc[0][3]);
            acc[0][4] = fmaf(a0, b1.x, acc[0][4]);
            acc[0][5] = fmaf(a0, b1.y, acc[0][5]);
            acc[0][6] = fmaf(a0, b1.z, acc[0][6]);
            acc[0][7] = fmaf(a0, b1.w, acc[0][7]);

            acc[1][0] = fmaf(a1, b0.x, acc[1][0]);
            acc[1][1] = fmaf(a1, b0.y, acc[1][1]);
            acc[1][2] = fmaf(a1, b0.z, acc[1][2]);
            acc[1][3] = fmaf(a1, b0.w, acc[1][3]);
            acc[1][4] = fmaf(a1, b1.x, acc[1][4]);
            acc[1][5] = fmaf(a1, b1.y, acc[1][5]);
            acc[1][6] = fmaf(a1, b1.z, acc[1][6]);
            acc[1][7] = fmaf(a1, b1.w, acc[1][7]);

            acc[2][0] = fmaf(a2, b0.x, acc[2][0]);
            acc[2][1] = fmaf(a2, b0.y, acc[2][1]);
            acc[2][2] = fmaf(a2, b0.z, acc[2][2]);
            acc[2][3] = fmaf(a2, b0.w, acc[2][3]);
            acc[2][4] = fmaf(a2, b1.x, acc[2][4]);
            acc[2][5] = fmaf(a2, b1.y, acc[2][5]);
            acc[2][6] = fmaf(a2, b1.z, acc[2][6]);
            acc[2][7] = fmaf(a2, b1.w, acc[2][7]);

            a0 = na0; a1 = na1; a2 = na2;
            b0 = nb0; b1 = nb1;
        }
    }

    // K-group 1 stores partials; group 0 adds and writes out.
    if (g == 1) {
        #pragma unroll
        for (int i = 0; i < 3; ++i) {
            int m = m0 + i;
            if (m < 44) {
                float* p = sP + m * DIMN + c0;
                *(float4*)p       = make_float4(acc[i][0], acc[i][1], acc[i][2], acc[i][3]);
                *(float4*)(p + 4) = make_float4(acc[i][4], acc[i][5], acc[i][6], acc[i][7]);
            }
        }
    }
    __syncthreads();
    if (g == 0) {
        const int rowbase = 40 + mb;
        #pragma unroll
        for (int i = 0; i < 3; ++i) {
            int m = m0 + i;
            if (m < 44) {
                const float* p = sP + m * DIMN + c0;
                float4 p0 = *(const float4*)p;
                float4 p1 = *(const float4*)(p + 4);
                float* o = O + (size_t)(rowbase + m) * DIMN + c0;
                *(float4*)o = make_float4(acc[i][0] + p0.x, acc[i][1] + p0.y,
                                          acc[i][2] + p0.z, acc[i][3] + p0.w);
                *(float4*)(o + 4) = make_float4(acc[i][4] + p1.x, acc[i][5] + p1.y,
                                                acc[i][6] + p1.z, acc[i][7] + p1.w);
            }
        }
    }
}

extern "C" void kernel_launch(void* const* d_in, const int* in_sizes, int n_in,
                              void* d_out, int out_size)
{
    const float* thetas = (const float*)d_in[0];
    const int*   ri     = (const int*)d_in[1];
    const int*   rj     = (const int*)d_in[2];
    float*       out    = (float*)d_out;

    const size_t smem1 = SM_FLOATS * sizeof(float);    // 103712 B
    const size_t smem2 = GSM_FLOATS * sizeof(float);   //  84480 B
    cudaFuncSetAttribute(givens_half_kernel,
                         cudaFuncAttributeMaxDynamicSharedMemorySize, (int)smem1);
    cudaFuncSetAttribute(combine_kernel,
                         cudaFuncAttributeMaxDynamicSharedMemorySize, (int)smem2);

    givens_half_kernel<<<2 * NHEADS, TPB, smem1>>>(thetas, ri, rj);
    combine_kernel<<<2 * NHEADS, GTPB, smem2>>>(out);
}